// round 17
// baseline (speedup 1.0000x reference)
#include <cuda_runtime.h>
#include <cstdint>
#include <math.h>

// GAT layer, v10 (mma.sync; tcgen05 unavailable on this build's sm_103 target):
//   v9 dense packing (BPC=8 -> 96 rows = 6 m16 tiles, warp = row-half x N-quarter,
//   2 CTAs/SM, row-major X smem stride 68, B from L2-hot WtF_g) with a
//   FULL-PREFETCH schedule:
//   - all 4 K-chunks staged to 4 resident smem buffers in the prologue
//     (4 cp.async commit groups); mainloop has no staging, one sync per chunk
//   - epilogue uses two half-CTA named barriers (batch data never crosses halves)

#define B_TOT   32768
#define N_NODE  12
#define F_IN    256
#define D_OUT   128
#define BPC     8
#define KC      64
#define XST     68             // X row stride in words: 68 % 32 == 4 -> conflict-free
#define HST     132            // Hs row stride (words)

#define XBUF_WORDS (96 * XST)              // 6528 per buffer
#define NBUF       4
#define ALIAS_WORDS (NBUF * XBUF_WORDS)    // 26112; Hs needs 96*132=12672 (buffers 0-1)

__device__ uint32_t WtF_g[4 * 64 * 32 * 4];   // [chunk][blk(ks,tp)][lane][v] tf32 bits

__device__ __forceinline__ uint32_t f2tf32(float f) {
    uint32_t r;
    asm("cvt.rna.tf32.f32 %0, %1;" : "=r"(r) : "f"(f));
    return r;
}

__device__ __forceinline__ void mma_tf32(float& c0, float& c1, float& c2, float& c3,
                                         uint32_t a0, uint32_t a1, uint32_t a2, uint32_t a3,
                                         uint32_t b0, uint32_t b1) {
    asm("mma.sync.aligned.m16n8k8.row.col.f32.tf32.tf32.f32 "
        "{%0,%1,%2,%3},{%4,%5,%6,%7},{%8,%9},{%0,%1,%2,%3};"
        : "+f"(c0), "+f"(c1), "+f"(c2), "+f"(c3)
        : "r"(a0), "r"(a1), "r"(a2), "r"(a3), "r"(b0), "r"(b1));
}

__device__ __forceinline__ uint32_t smem_u32(const void* p) {
    uint32_t a;
    asm("{ .reg .u64 t; cvta.to.shared.u64 t, %1; cvt.u32.u64 %0, t; }" : "=r"(a) : "l"(p));
    return a;
}

__device__ __forceinline__ void cp16(uint32_t dst, const void* src) {
    asm volatile("cp.async.ca.shared.global [%0], [%1], 16;" :: "r"(dst), "l"(src));
}
__device__ __forceinline__ void cp_commit() {
    asm volatile("cp.async.commit_group;");
}
template <int N>
__device__ __forceinline__ void cp_wait() {
    asm volatile("cp.async.wait_group %0;" :: "n"(N) : "memory");
}

__device__ __forceinline__ float elu_f(float v) {
    return v > 0.f ? v : expm1f(v);
}

// ---- pre-kernel: fragment-ordered tf32 W (unchanged layout) ----------------
// word (ch, blk=(ks,tp), lane=(qq,mm), v=(tl,hi)) = tf32(W[k][n]),
//   k = 64ch + 8ks + mm + 4hi,  n = 16tp + 8tl + qq
__global__ void wfrag_pre_kernel(const float* __restrict__ W) {
    int idx = blockIdx.x * 256 + threadIdx.x;      // 0..32767
    int v   = idx & 3;
    int l   = (idx >> 2) & 31;
    int blk = (idx >> 7) & 63;
    int ch  = idx >> 13;
    int qq = l >> 2, mm = l & 3;
    int tl = v >> 1, hi = v & 1;
    int ks = blk >> 3, tp = blk & 7;
    int k = ch * 64 + ks * 8 + mm + 4 * hi;
    int n = 16 * tp + 8 * tl + qq;
    WtF_g[idx] = f2tf32(W[k * D_OUT + n]);
}

// stage X chunk c into buffer c: warp copies its own batch's 12 rows (16B pieces)
__device__ __forceinline__ void stage_x(uint32_t sbX, int c,
                                        const float* __restrict__ xw,
                                        int w, int lane) {
    const uint32_t bw = (uint32_t)c * XBUF_WORDS;
    #pragma unroll
    for (int it = 0; it < 6; it++) {
        int il  = it * 32 + lane;      // 0..191 = 12 rows x 16 float4
        int row = il >> 4;             // node 0..11
        int c4  = il & 15;
        const float* src = xw + row * F_IN + c * KC + 4 * c4;
        uint32_t dst = sbX + (bw + (w * N_NODE + row) * XST + 4 * c4) * 4;
        cp16(dst, src);
    }
    cp_commit();
}

__global__ void __launch_bounds__(256, 2)
gat_fused_kernel(const float* __restrict__ x,    // [B, N, F]
                 const float* __restrict__ adj,  // [N, N]
                 const float* __restrict__ a,    // [2D, 1]
                 float* __restrict__ out)        // [B, N, D]
{
    extern __shared__ uint32_t smem[];
    uint32_t* XsF    = smem;                      // 4 row-major buffers
    float*    Hs     = (float*)smem;              // aliases buffers 0-1 post-GEMM
    float*    sA     = (float*)(smem + ALIAS_WORDS);
    float*    adjS   = sA + 2 * D_OUT;
    float*    alphaS = adjS + N_NODE * N_NODE;    // [8][144], row stride 12

    const uint32_t sbX = smem_u32(XsF);

    const int tid  = threadIdx.x;
    const int w    = tid >> 5;
    const int lane = tid & 31;
    const int g    = w >> 2;          // row half: m-tiles 3g..3g+2
    const int nq   = w & 3;           // N quarter: cols 32nq..32nq+31
    const int qq   = lane >> 2;
    const int m    = lane & 3;
    const int b    = blockIdx.x * BPC + w;

    sA[tid] = a[tid];
    if (tid < N_NODE * N_NODE) adjS[tid] = adj[tid];

    float acc[3][4][4];
    #pragma unroll
    for (int u = 0; u < 3; u++)
        #pragma unroll
        for (int v = 0; v < 4; v++)
            acc[u][v][0] = acc[u][v][1] = acc[u][v][2] = acc[u][v][3] = 0.f;

    const float* xw = x + ((size_t)b * N_NODE) * F_IN;   // warp's batch

    // prologue: stage ALL 4 chunks (4 commit groups, latency amortized)
    stage_x(sbX, 0, xw, w, lane);
    stage_x(sbX, 1, xw, w, lane);
    stage_x(sbX, 2, xw, w, lane);
    stage_x(sbX, 3, xw, w, lane);

    #pragma unroll
    for (int c = 0; c < 4; c++) {
        if      (c == 0) cp_wait<3>();
        else if (c == 1) cp_wait<2>();
        else if (c == 2) cp_wait<1>();
        else             cp_wait<0>();
        __syncthreads();   // chunk-c data (all warps) visible; c=0 also covers sA/adjS

        const uint32_t bw = (uint32_t)c * XBUF_WORDS;
        // per-warp A base: row (48g + qq), col m (tile u adds 16 rows, ks adds 8 cols)
        const uint32_t* Xa = XsF + bw + (48 * g + qq) * XST + m;
        const uint4* __restrict__ Wg =
            (const uint4*)WtF_g + ((size_t)c * 64 + 2 * nq) * 32 + lane;

        #pragma unroll
        for (int ks = 0; ks < 8; ks++) {
            const int k0 = ks * 8;
            uint4 Bf0 = Wg[(ks * 8 + 0) * 32];
            uint4 Bf1 = Wg[(ks * 8 + 1) * 32];

            #pragma unroll
            for (int u = 0; u < 3; u++) {
                const uint32_t* Ap = Xa + u * 16 * XST + k0;
                uint32_t a0 = Ap[0];
                uint32_t a1 = Ap[8 * XST];
                uint32_t a2 = Ap[4];
                uint32_t a3 = Ap[8 * XST + 4];

                mma_tf32(acc[u][0][0], acc[u][0][1], acc[u][0][2], acc[u][0][3],
                         a0, a1, a2, a3, Bf0.x, Bf0.y);
                mma_tf32(acc[u][1][0], acc[u][1][1], acc[u][1][2], acc[u][1][3],
                         a0, a1, a2, a3, Bf0.z, Bf0.w);
                mma_tf32(acc[u][2][0], acc[u][2][1], acc[u][2][2], acc[u][2][3],
                         a0, a1, a2, a3, Bf1.x, Bf1.y);
                mma_tf32(acc[u][3][0], acc[u][3][1], acc[u][3][2], acc[u][3][3],
                         a0, a1, a2, a3, Bf1.z, Bf1.w);
            }
        }
        // no trailing sync: next chunk's data is in a different buffer; H spill
        // (buffers 0-1) is disjoint from chunk-3 reads (buffer 3).
    }

    // ---- spill H (96 dense rows x 128) into Hs (aliases buffers 0-1) -------
    #pragma unroll
    for (int u = 0; u < 3; u++) {
        const int row0 = (3 * g + u) * 16 + qq;
        #pragma unroll
        for (int v = 0; v < 4; v++) {
            int col = 32 * nq + 8 * v + 2 * m;
            float* r0p = Hs + row0 * HST + col;
            *(float2*)r0p = make_float2(acc[u][v][0], acc[u][v][1]);
            *(float2*)(r0p + 8 * HST) = make_float2(acc[u][v][2], acc[u][v][3]);
        }
    }
    // half-CTA barrier: batch b's rows are written & read within one g-half
    asm volatile("bar.sync %0, 128;" :: "r"(1 + g) : "memory");

    // ---- dots + masked softmax (warp w owns batch w; lane = row i) ---------
    float sj = 0.f, si = 0.f;
    if (lane < N_NODE) {
        const float4* hr  = (const float4*)(Hs + (w * N_NODE + lane) * HST);
        const float4* ajp = (const float4*)sA;
        const float4* aip = (const float4*)(sA + D_OUT);
        #pragma unroll
        for (int cc = 0; cc < 32; cc++) {
            float4 hv = hr[cc];
            float4 av = ajp[cc], bv = aip[cc];
            sj += hv.x*av.x + hv.y*av.y + hv.z*av.z + hv.w*av.w;
            si += hv.x*bv.x + hv.y*bv.y + hv.z*bv.z + hv.w*bv.w;
        }
    }
    float sjv[N_NODE];
    #pragma unroll
    for (int j = 0; j < N_NODE; j++)
        sjv[j] = __shfl_sync(0xffffffffu, sj, j);

    if (lane < N_NODE) {
        float ev[N_NODE];
        float mx = -INFINITY;
        #pragma unroll
        for (int j = 0; j < N_NODE; j++) {
            float e = si + sjv[j];
            e = e > 0.f ? e : 0.2f * e;
            ev[j] = (adjS[lane * N_NODE + j] == 1.0f) ? e : -INFINITY;
            mx = fmaxf(mx, ev[j]);
        }
        float sum = 0.f;
        #pragma unroll
        for (int j = 0; j < N_NODE; j++) { ev[j] = __expf(ev[j] - mx); sum += ev[j]; }
        float inv = 1.f / sum;
        float* ap = alphaS + w * 144 + lane * 12;
        *(float4*)(ap)     = make_float4(ev[0]*inv, ev[1]*inv, ev[2]*inv,  ev[3]*inv);
        *(float4*)(ap + 4) = make_float4(ev[4]*inv, ev[5]*inv, ev[6]*inv,  ev[7]*inv);
        *(float4*)(ap + 8) = make_float4(ev[8]*inv, ev[9]*inv, ev[10]*inv, ev[11]*inv);
    }
    __syncwarp();

    // ---- h' = alpha @ H (float4 alpha loads), elu, store -------------------
    float4 o[N_NODE];
    #pragma unroll
    for (int i = 0; i < N_NODE; i++) o[i] = make_float4(0.f, 0.f, 0.f, 0.f);

    const float* hb  = Hs + (w * N_NODE) * HST + lane * 4;
    const float* alw = alphaS + w * 144;
    #pragma unroll
    for (int jb = 0; jb < 3; jb++) {
        float4 h0 = *(const float4*)(hb + (4 * jb + 0) * HST);
        float4 h1 = *(const float4*)(hb + (4 * jb + 1) * HST);
        float4 h2 = *(const float4*)(hb + (4 * jb + 2) * HST);
        float4 h3 = *(const float4*)(hb + (4 * jb + 3) * HST);
        #pragma unroll
        for (int i = 0; i < N_NODE; i++) {
            float4 av = *(const float4*)(alw + i * 12 + 4 * jb);
            o[i].x += av.x*h0.x + av.y*h1.x + av.z*h2.x + av.w*h3.x;
            o[i].y += av.x*h0.y + av.y*h1.y + av.z*h2.y + av.w*h3.y;
            o[i].z += av.x*h0.z + av.y*h1.z + av.z*h2.z + av.w*h3.z;
            o[i].w += av.x*h0.w + av.y*h1.w + av.z*h2.w + av.w*h3.w;
        }
    }
    #pragma unroll
    for (int i = 0; i < N_NODE; i++) {
        float4 r;
        r.x = elu_f(o[i].x);
        r.y = elu_f(o[i].y);
        r.z = elu_f(o[i].z);
        r.w = elu_f(o[i].w);
        *(float4*)(out + ((size_t)b * N_NODE + i) * D_OUT + lane * 4) = r;
    }
}

extern "C" void kernel_launch(void* const* d_in, const int* in_sizes, int n_in,
                              void* d_out, int out_size) {
    const float* x   = (const float*)d_in[0];   // [32768,12,256]
    const float* adj = (const float*)d_in[1];   // [12,12]
    const float* W   = (const float*)d_in[2];   // [256,128]
    const float* a   = (const float*)d_in[3];   // [256,1]
    float* out       = (float*)d_out;           // [32768,12,128]

    wfrag_pre_kernel<<<128, 256>>>(W);

    const int smem_bytes =
        (ALIAS_WORDS + 2 * D_OUT + N_NODE * N_NODE + BPC * 144) * 4;

    cudaFuncSetAttribute(gat_fused_kernel,
                         cudaFuncAttributeMaxDynamicSharedMemorySize, smem_bytes);

    gat_fused_kernel<<<B_TOT / BPC, 256, smem_bytes>>>(x, adj, a, out);
}